// round 1
// baseline (speedup 1.0000x reference)
#include <cuda_runtime.h>
#include <cstdint>
#include <cstddef>

#define KT 16      // K chunk
#define MT 128     // M tile (spatial positions per block)
#define NTP 96     // padded N (85 -> 96)
#define NOUT 85
#define THREADS 256

// ---------- packed f32x2 helpers (Blackwell FFMA2 path) ----------
__device__ __forceinline__ unsigned long long pack2(float lo, float hi) {
    unsigned long long r;
    asm("mov.b64 %0, {%1, %2};" : "=l"(r) : "f"(lo), "f"(hi));
    return r;
}
__device__ __forceinline__ float2 unpack2(unsigned long long v) {
    float2 f;
    asm("mov.b64 {%0, %1}, %2;" : "=f"(f.x), "=f"(f.y) : "l"(v));
    return f;
}
__device__ __forceinline__ void ffma2(unsigned long long& d,
                                      unsigned long long a,
                                      unsigned long long b) {
    asm("fma.rn.f32x2 %0, %1, %2, %0;" : "+l"(d) : "l"(a), "l"(b));
}

// ---------- cp.async ----------
__device__ __forceinline__ void cp_async16(uint32_t dst_smem, const void* src, int src_bytes) {
    asm volatile("cp.async.cg.shared.global [%0], [%1], 16, %2;"
                 :: "r"(dst_smem), "l"(src), "r"(src_bytes));
}
__device__ __forceinline__ void cp_commit() { asm volatile("cp.async.commit_group;"); }
__device__ __forceinline__ void cp_wait0()  { asm volatile("cp.async.wait_group 0;"); }

// out[b, o, hw] = sum_c feat[b, c, hw] * W[o, c] + bias[o]
// GEMM view per batch:  D[m, n] = sum_k A[k, m] * B[k, n]
//   A[k, m] = feat[b, k, m]  (m contiguous -> coalesced)
//   B[k, n] = W[n, k]
__global__ __launch_bounds__(THREADS, 2)
void head1x1_kernel(const float* __restrict__ feat,
                    const float* __restrict__ W,
                    const float* __restrict__ bias,
                    float* __restrict__ out,
                    int C, int HW)
{
    __shared__ float sA[2][KT][MT];   // 16 KB
    __shared__ float sB[2][KT][NTP];  // 12 KB

    const int b  = blockIdx.y;
    const int m0 = blockIdx.x * MT;
    const float* fb = feat + (size_t)b * C * HW;
    float* ob = out + (size_t)b * NOUT * HW;

    const int tid   = threadIdx.x;
    const int mg    = tid & 31;   // lane: m-group (4 consecutive m each)
    const int ng    = tid >> 5;   // warp id: n-group (12 n each) -> B reads broadcast per warp
    const int nbase = ng * 12;

    // ---- A tile load mapping: 2 float4 per thread ----
    const int ca  = tid & 31;       // float4 column (0..31) -> m = ca*4
    const int ka0 = tid >> 5;       // k rows 0..7
    const int ka1 = ka0 + 8;        // k rows 8..15
    const int amA = m0 + ca * 4;
    const bool a_ok = (amA < HW);   // HW % 4 == 0 and amA % 4 == 0 -> full float4 valid
    const int a_bytes = a_ok ? 16 : 0;
    const size_t a_col = a_ok ? (size_t)amA : 0; // clamp OOB pointer

    const uint32_t sA0_dst0 = (uint32_t)__cvta_generic_to_shared(&sA[0][ka0][ca * 4]);
    const uint32_t sA0_dst1 = (uint32_t)__cvta_generic_to_shared(&sA[0][ka1][ca * 4]);
    const uint32_t sA1_dst0 = (uint32_t)__cvta_generic_to_shared(&sA[1][ka0][ca * 4]);
    const uint32_t sA1_dst1 = (uint32_t)__cvta_generic_to_shared(&sA[1][ka1][ca * 4]);

    // ---- B tile load mapping: 6 scalars per thread ----
    // idx = tid + i*256; kb = idx & 15 (== tid & 15), nb = (tid >> 4) + 16*i
    const int kb  = tid & 15;
    const int nb0 = tid >> 4;

    const int nch = C / KT;

    // ---------------- prologue: chunk 0 -> buffer 0 ----------------
    {
        cp_async16(sA0_dst0, fb + (size_t)ka0 * HW + a_col, a_bytes);
        cp_async16(sA0_dst1, fb + (size_t)ka1 * HW + a_col, a_bytes);
        cp_commit();
#pragma unroll
        for (int i = 0; i < 6; i++) {
            const int nb = nb0 + 16 * i;
            float v = 0.f;
            if (nb < NOUT) v = __ldg(&W[(size_t)nb * C + kb]);
            sB[0][kb][nb] = v;
        }
        cp_wait0();
        __syncthreads();
    }

    // ---------------- accumulators (init with bias) ----------------
    unsigned long long acc[4][6];
#pragma unroll
    for (int j = 0; j < 6; j++) {
        const int nlo = nbase + 2 * j;
        const int nhi = nlo + 1;
        const float blo = (nlo < NOUT) ? __ldg(&bias[nlo]) : 0.f;
        const float bhi = (nhi < NOUT) ? __ldg(&bias[nhi]) : 0.f;
        const unsigned long long bb = pack2(blo, bhi);
#pragma unroll
        for (int m = 0; m < 4; m++) acc[m][j] = bb;
    }

    // ---------------- main loop ----------------
    for (int t = 0; t < nch; t++) {
        const int cur = t & 1;
        const int nxt = cur ^ 1;
        const bool has_next = (t + 1) < nch;

        float breg[6];
        if (has_next) {
            const int c0n = (t + 1) * KT;
            // issue B global loads early (land during compute)
#pragma unroll
            for (int i = 0; i < 6; i++) {
                const int nb = nb0 + 16 * i;
                breg[i] = (nb < NOUT) ? __ldg(&W[(size_t)nb * C + c0n + kb]) : 0.f;
            }
            // async A prefetch into nxt buffer
            const uint32_t d0 = nxt ? sA1_dst0 : sA0_dst0;
            const uint32_t d1 = nxt ? sA1_dst1 : sA0_dst1;
            cp_async16(d0, fb + (size_t)(c0n + ka0) * HW + a_col, a_bytes);
            cp_async16(d1, fb + (size_t)(c0n + ka1) * HW + a_col, a_bytes);
            cp_commit();
        }

        // compute on cur buffer
#pragma unroll
        for (int k = 0; k < KT; k++) {
            const float4 a = *reinterpret_cast<const float4*>(&sA[cur][k][mg * 4]);
            const ulonglong2* pb =
                reinterpret_cast<const ulonglong2*>(&sB[cur][k][nbase]);
            const ulonglong2 u0 = pb[0];
            const ulonglong2 u1 = pb[1];
            const ulonglong2 u2 = pb[2];
            const unsigned long long bb[6] = {u0.x, u0.y, u1.x, u1.y, u2.x, u2.y};

            const unsigned long long a0 = pack2(a.x, a.x);
            const unsigned long long a1 = pack2(a.y, a.y);
            const unsigned long long a2 = pack2(a.z, a.z);
            const unsigned long long a3 = pack2(a.w, a.w);
#pragma unroll
            for (int j = 0; j < 6; j++) {
                ffma2(acc[0][j], a0, bb[j]);
                ffma2(acc[1][j], a1, bb[j]);
                ffma2(acc[2][j], a2, bb[j]);
                ffma2(acc[3][j], a3, bb[j]);
            }
        }

        if (has_next) {
#pragma unroll
            for (int i = 0; i < 6; i++) {
                const int nb = nb0 + 16 * i;
                sB[nxt][kb][nb] = breg[i];
            }
        }
        cp_wait0();
        __syncthreads();
    }

    // ---------------- epilogue: coalesced float4 stores along m ----------------
    const int ms = m0 + mg * 4;
    if (ms < HW) {
#pragma unroll
        for (int j = 0; j < 6; j++) {
            const int nlo = nbase + 2 * j;
            const int nhi = nlo + 1;
            const float2 v0 = unpack2(acc[0][j]);
            const float2 v1 = unpack2(acc[1][j]);
            const float2 v2 = unpack2(acc[2][j]);
            const float2 v3 = unpack2(acc[3][j]);
            if (nlo < NOUT) {
                float4 o = make_float4(v0.x, v1.x, v2.x, v3.x);
                *reinterpret_cast<float4*>(&ob[(size_t)nlo * HW + ms]) = o;
            }
            if (nhi < NOUT) {
                float4 o = make_float4(v0.y, v1.y, v2.y, v3.y);
                *reinterpret_cast<float4*>(&ob[(size_t)nhi * HW + ms]) = o;
            }
        }
    }
}

extern "C" void kernel_launch(void* const* d_in, const int* in_sizes, int n_in,
                              void* d_out, int out_size)
{
    // Identify inputs by element count (robust to metadata ordering).
    const float* feat[3] = {nullptr, nullptr, nullptr};
    const float* wgt[3]  = {nullptr, nullptr, nullptr};
    const float* bia[3]  = {nullptr, nullptr, nullptr};
    int bcount = 0;
    for (int i = 0; i < n_in; i++) {
        const int s = in_sizes[i];
        const float* p = (const float*)d_in[i];
        if      (s == 16 * 256 * 6400)  feat[0] = p;
        else if (s == 16 * 512 * 1600)  feat[1] = p;
        else if (s == 16 * 1024 * 400)  feat[2] = p;
        else if (s == 85 * 256)         wgt[0] = p;
        else if (s == 85 * 512)         wgt[1] = p;
        else if (s == 85 * 1024)        wgt[2] = p;
        else if (s == 85 && bcount < 3) bia[bcount++] = p;
    }

    float* out = (float*)d_out;
    const size_t o0 = 0;
    const size_t o1 = (size_t)16 * 85 * 6400;            // after out0
    const size_t o2 = o1 + (size_t)16 * 85 * 1600;       // after out1

    head1x1_kernel<<<dim3(50, 16), THREADS>>>(feat[0], wgt[0], bia[0], out + o0, 256,  6400);
    head1x1_kernel<<<dim3(13, 16), THREADS>>>(feat[1], wgt[1], bia[1], out + o1, 512,  1600);
    head1x1_kernel<<<dim3(4,  16), THREADS>>>(feat[2], wgt[2], bia[2], out + o2, 1024, 400);
}

// round 4
// speedup vs baseline: 4.0659x; 4.0659x over previous
#include <cuda_runtime.h>
#include <cstdint>
#include <cstddef>

#define THREADS 256
#define NOUT 85

// smem float strides (chosen for conflict-free fragment access)
#define SA_STRIDE 136   // A tile [32 k][128 m] rows padded 128->136
#define SB_STRIDE 36    // B tile [96 n][32 k]  rows padded 32->36
#define SO_STRIDE 132   // out tile [96 n][128 m] rows padded 128->132

#define SA_BASE 0
#define SB_BASE (32 * SA_STRIDE)                  // 4352 floats
#define SMEM_FLOATS_OUT (96 * SO_STRIDE)          // 12672
#define DSMEM_BYTES (SMEM_FLOATS_OUT * 4)         // 50688 (>= staging 31232)

// tf32 destination is .b32 in PTX — return the bit pattern.
__device__ __forceinline__ uint32_t f2tf32(float x) {
    uint32_t r; asm("cvt.rna.tf32.f32 %0, %1;" : "=r"(r) : "f"(x)); return r;
}

__device__ __forceinline__ void mma_tf32(float c[4], const uint32_t a[4], const uint32_t b[2]) {
    asm volatile(
        "mma.sync.aligned.m16n8k8.row.col.f32.tf32.tf32.f32 "
        "{%0,%1,%2,%3}, {%4,%5,%6,%7}, {%8,%9}, {%0,%1,%2,%3};"
        : "+f"(c[0]), "+f"(c[1]), "+f"(c[2]), "+f"(c[3])
        : "r"(a[0]), "r"(a[1]), "r"(a[2]), "r"(a[3]), "r"(b[0]), "r"(b[1]));
}

// out[b, o, hw] = sum_c feat[b, c, hw] * W[o, c] + bias[o]
// GEMM: D[m, n], m = flat b*HW+hw (128-tile), n = o (85 -> 96), k = c.
__global__ __launch_bounds__(THREADS, 2)
void head_mma_kernel(const float* __restrict__ f0, const float* __restrict__ f1,
                     const float* __restrict__ f2,
                     const float* __restrict__ w0, const float* __restrict__ w1,
                     const float* __restrict__ w2,
                     const float* __restrict__ bi0, const float* __restrict__ bi1,
                     const float* __restrict__ bi2,
                     float* __restrict__ out)
{
    extern __shared__ float sm[];
    uint32_t* smu = reinterpret_cast<uint32_t*>(sm);

    const int tid  = threadIdx.x;
    const int wid  = tid >> 5;
    const int lane = tid & 31;

    // ---- level dispatch: heavy CTAs first for wave balance ----
    const float* feat; const float* W; const float* bias; float* ob;
    int C, HW, nch, ntile;
    const int bid = blockIdx.x;
    if (bid < 50)       { feat = f2; W = w2; bias = bi2; ob = out + 10880000; C = 1024; HW = 400;  nch = 32; ntile = bid; }
    else if (bid < 250) { feat = f1; W = w1; bias = bi1; ob = out + 8704000;  C = 512;  HW = 1600; nch = 16; ntile = bid - 50; }
    else                { feat = f0; W = w0; bias = bi0; ob = out;            C = 256;  HW = 6400; nch = 8;  ntile = bid - 250; }

    const int m0 = ntile * 128;

    // ---- A staging mapping: 4 float4 loads per thread per chunk ----
    // idx = tid + 256*i over 1024 float4 slots: k = idx>>5, mq = idx&31
    int aK[4]; size_t aSrcOff[4]; int aDst[4];
#pragma unroll
    for (int i = 0; i < 4; i++) {
        const int idx = tid + 256 * i;
        const int k = idx >> 5;
        const int mq = idx & 31;
        const int p = m0 + mq * 4;         // flat position (float4 never crosses batch: HW%4==0)
        const int b = p / HW;
        const int hw = p - b * HW;
        aK[i] = k;
        aSrcOff[i] = (size_t)b * C * HW + hw;   // + (kc + k)*HW at use
        aDst[i] = SA_BASE + k * SA_STRIDE + mq * 4;
    }

    // ---- B staging mapping: 3 float4 loads per thread per chunk ----
    // n = (tid>>3) + 32*j (0..95), kq = tid&7
    const int bKq = tid & 7;
    const int bN0 = tid >> 3;

    // ---- warp tile ----
    const int wm = wid & 1;        // M half (64 rows)
    const int wn = wid >> 1;       // N quarter (24 cols)
    const int g  = lane >> 2;      // group id 0..7
    const int tg = lane & 3;       // thread-in-group 0..3
    const int mA = wm * 64 + g;
    const int nB = wn * 24 + g;

    float acc[4][3][4];
#pragma unroll
    for (int i = 0; i < 4; i++)
#pragma unroll
        for (int j = 0; j < 3; j++)
#pragma unroll
            for (int r = 0; r < 4; r++) acc[i][j][r] = 0.f;

    // ---- prologue: prefetch chunk 0 into regs ----
    float4 ra[4], rb[3];
#pragma unroll
    for (int i = 0; i < 4; i++)
        ra[i] = *reinterpret_cast<const float4*>(feat + aSrcOff[i] + (size_t)aK[i] * HW);
#pragma unroll
    for (int j = 0; j < 3; j++) {
        const int n = bN0 + 32 * j;
        rb[j] = (n < NOUT) ? *reinterpret_cast<const float4*>(W + (size_t)n * C + bKq * 4)
                           : make_float4(0.f, 0.f, 0.f, 0.f);
    }

    for (int t = 0; t < nch; t++) {
        __syncthreads();   // previous compute finished reading smem

        // ---- STS staged chunk (with tf32 rounding) ----
#pragma unroll
        for (int i = 0; i < 4; i++) {
            uint4 w;
            w.x = f2tf32(ra[i].x); w.y = f2tf32(ra[i].y);
            w.z = f2tf32(ra[i].z); w.w = f2tf32(ra[i].w);
            *reinterpret_cast<uint4*>(&smu[aDst[i]]) = w;
        }
#pragma unroll
        for (int j = 0; j < 3; j++) {
            uint4 w;
            w.x = f2tf32(rb[j].x); w.y = f2tf32(rb[j].y);
            w.z = f2tf32(rb[j].z); w.w = f2tf32(rb[j].w);
            const int n = bN0 + 32 * j;
            *reinterpret_cast<uint4*>(&smu[SB_BASE + n * SB_STRIDE + bKq * 4]) = w;
        }
        __syncthreads();

        // ---- prefetch next chunk ----
        if (t + 1 < nch) {
            const int kc = (t + 1) * 32;
#pragma unroll
            for (int i = 0; i < 4; i++)
                ra[i] = *reinterpret_cast<const float4*>(feat + aSrcOff[i] + (size_t)(kc + aK[i]) * HW);
#pragma unroll
            for (int j = 0; j < 3; j++) {
                const int n = bN0 + 32 * j;
                rb[j] = (n < NOUT) ? *reinterpret_cast<const float4*>(W + (size_t)n * C + kc + bKq * 4)
                                   : make_float4(0.f, 0.f, 0.f, 0.f);
            }
        }

        // ---- compute: 4 k-steps of m16n8k8 ----
#pragma unroll
        for (int ks = 0; ks < 4; ks++) {
            const int k0 = ks * 8 + tg;
            uint32_t afr[4][4];
#pragma unroll
            for (int i = 0; i < 4; i++) {
                const int mm = mA + 16 * i;
                afr[i][0] = smu[SA_BASE + k0 * SA_STRIDE + mm];
                afr[i][1] = smu[SA_BASE + k0 * SA_STRIDE + mm + 8];
                afr[i][2] = smu[SA_BASE + (k0 + 4) * SA_STRIDE + mm];
                afr[i][3] = smu[SA_BASE + (k0 + 4) * SA_STRIDE + mm + 8];
            }
            uint32_t bfr[3][2];
#pragma unroll
            for (int j = 0; j < 3; j++) {
                const int nn = nB + 8 * j;
                bfr[j][0] = smu[SB_BASE + nn * SB_STRIDE + k0];
                bfr[j][1] = smu[SB_BASE + nn * SB_STRIDE + k0 + 4];
            }
#pragma unroll
            for (int i = 0; i < 4; i++)
#pragma unroll
                for (int j = 0; j < 3; j++)
                    mma_tf32(acc[i][j], afr[i], bfr[j]);
        }
    }

    // ---- epilogue: transpose via smem, coalesced stores ----
    __syncthreads();
    {
        const int mBase = wm * 64 + g;
        const int nBase = wn * 24 + tg * 2;
#pragma unroll
        for (int i = 0; i < 4; i++) {
#pragma unroll
            for (int j = 0; j < 3; j++) {
                const int n = nBase + 8 * j;
                const int m = mBase + 16 * i;
                sm[n * SO_STRIDE + m]            = acc[i][j][0];
                sm[(n + 1) * SO_STRIDE + m]      = acc[i][j][1];
                sm[n * SO_STRIDE + m + 8]        = acc[i][j][2];
                sm[(n + 1) * SO_STRIDE + m + 8]  = acc[i][j][3];
            }
        }
    }
    __syncthreads();

#pragma unroll
    for (int j2 = 0; j2 < 12; j2++) {
        const int idx = j2 * 256 + tid;
        const int n = idx >> 5;        // 0..95
        const int mq = idx & 31;
        if (n < NOUT) {
            float4 v = *reinterpret_cast<const float4*>(&sm[n * SO_STRIDE + mq * 4]);
            const float bo = __ldg(&bias[n]);
            v.x += bo; v.y += bo; v.z += bo; v.w += bo;
            const int p = m0 + mq * 4;
            const int b = p / HW;
            const int hw = p - b * HW;
            *reinterpret_cast<float4*>(ob + ((size_t)b * NOUT + n) * HW + hw) = v;
        }
    }
}

extern "C" void kernel_launch(void* const* d_in, const int* in_sizes, int n_in,
                              void* d_out, int out_size)
{
    const float* feat[3] = {nullptr, nullptr, nullptr};
    const float* wgt[3]  = {nullptr, nullptr, nullptr};
    const float* bia[3]  = {nullptr, nullptr, nullptr};
    int bcount = 0;
    for (int i = 0; i < n_in; i++) {
        const int s = in_sizes[i];
        const float* p = (const float*)d_in[i];
        if      (s == 16 * 256 * 6400)  feat[0] = p;
        else if (s == 16 * 512 * 1600)  feat[1] = p;
        else if (s == 16 * 1024 * 400)  feat[2] = p;
        else if (s == 85 * 256)         wgt[0] = p;
        else if (s == 85 * 512)         wgt[1] = p;
        else if (s == 85 * 1024)        wgt[2] = p;
        else if (s == 85 && bcount < 3) bia[bcount++] = p;
    }

    cudaFuncSetAttribute(head_mma_kernel,
                         cudaFuncAttributeMaxDynamicSharedMemorySize, DSMEM_BYTES);

    head_mma_kernel<<<1050, THREADS, DSMEM_BYTES>>>(
        feat[0], feat[1], feat[2],
        wgt[0], wgt[1], wgt[2],
        bia[0], bia[1], bia[2],
        (float*)d_out);
}